// round 2
// baseline (speedup 1.0000x reference)
#include <cuda_runtime.h>
#include <math.h>

// Problem constants
#define TS     32
#define BB     32
#define NNODE  512
#define DIN    128
#define HID    128
#define KTOT   768                 // 3 * (D + H)
#define ROWS   (BB * NNODE)        // 16384
#define BNH    (BB * NNODE * HID)  // 2097152
#define FINALS (2 * BNH)           // offset of "current" region in d_out

// GEMM tile config
#define BM 128
#define BN 64
#define BK 16
#define NTHREADS 256

// Scratch (allocation-free: __device__ globals)
__device__ float g_M2[NNODE * NNODE];                // 2*S*S - I
__device__ float g_A[(size_t)ROWS * KTOT];           // [x | h/rh | d1 | d2]
__device__ float g_h[BNH];
__device__ float g_u[BNH];
__device__ float g_rh[BNH];
__device__ float g_l0out[(size_t)TS * BNH];          // layer-0 outputs (256 MB)

// ---------------------------------------------------------------------------
// M2 = 2 * S @ S - I     (512x512x512)
// ---------------------------------------------------------------------------
__global__ __launch_bounds__(NTHREADS) void m2_kernel(const float* __restrict__ S) {
    __shared__ float As[BK][BM + 4];
    __shared__ float Bs[BK][BN];
    const int tid = threadIdx.x;
    const int m0 = blockIdx.x * BM;
    const int n0 = blockIdx.y * BN;
    const int tm = tid >> 4, tn = tid & 15;

    float acc[8][4];
#pragma unroll
    for (int i = 0; i < 8; i++)
#pragma unroll
        for (int j = 0; j < 4; j++) acc[i][j] = 0.f;

    for (int kt = 0; kt < NNODE; kt += BK) {
#pragma unroll
        for (int it = 0; it < 2; it++) {
            int idx = tid + it * NTHREADS;
            int row = idx >> 2, k4 = (idx & 3) * 4;
            float4 v = *(const float4*)&S[(size_t)(m0 + row) * NNODE + kt + k4];
            As[k4 + 0][row] = v.x; As[k4 + 1][row] = v.y;
            As[k4 + 2][row] = v.z; As[k4 + 3][row] = v.w;
        }
        {
            int krow = tid >> 4, f4 = (tid & 15) * 4;
            float4 v = *(const float4*)&S[(size_t)(kt + krow) * NNODE + n0 + f4];
            *(float4*)&Bs[krow][f4] = v;
        }
        __syncthreads();
#pragma unroll
        for (int kk = 0; kk < BK; kk++) {
            float a[8], b[4];
#pragma unroll
            for (int i = 0; i < 8; i++) a[i] = As[kk][tm * 8 + i];
#pragma unroll
            for (int j = 0; j < 4; j++) b[j] = Bs[kk][tn * 4 + j];
#pragma unroll
            for (int i = 0; i < 8; i++)
#pragma unroll
                for (int j = 0; j < 4; j++) acc[i][j] += a[i] * b[j];
        }
        __syncthreads();
    }
#pragma unroll
    for (int i = 0; i < 8; i++) {
        int m = m0 + tm * 8 + i;
#pragma unroll
        for (int j = 0; j < 4; j++) {
            int n = n0 + tn * 4 + j;
            g_M2[(size_t)m * NNODE + n] = 2.0f * acc[i][j] - (m == n ? 1.0f : 0.0f);
        }
    }
}

// ---------------------------------------------------------------------------
// Batched diffusion: for each batch b, out[b, m, ob+f] = sum_n M[m,n] * g_A[b,n, in_base+f]
// grid.z in [0, 2*BB): z < BB -> mat=S (out at outS), else mat=M2 (out at outM2)
// grid.x = 512/BM, grid.y = ncols/BN
// ---------------------------------------------------------------------------
__global__ __launch_bounds__(NTHREADS) void diff_kernel(const float* __restrict__ S,
                                                        int in_base, int outS, int outM2) {
    __shared__ float As[BK][BM + 4];
    __shared__ float Bs[BK][BN];
    const int z = blockIdx.z;
    const int matsel = (z >= BB);
    const int b = matsel ? z - BB : z;
    const float* __restrict__ M = matsel ? g_M2 : S;
    const int ob = matsel ? outM2 : outS;

    const int tid = threadIdx.x;
    const int m0 = blockIdx.x * BM;
    const int n0 = blockIdx.y * BN;
    const int tm = tid >> 4, tn = tid & 15;
    const size_t rowbase = (size_t)b * NNODE;

    float acc[8][4];
#pragma unroll
    for (int i = 0; i < 8; i++)
#pragma unroll
        for (int j = 0; j < 4; j++) acc[i][j] = 0.f;

    for (int kt = 0; kt < NNODE; kt += BK) {
#pragma unroll
        for (int it = 0; it < 2; it++) {
            int idx = tid + it * NTHREADS;
            int row = idx >> 2, k4 = (idx & 3) * 4;
            float4 v = *(const float4*)&M[(size_t)(m0 + row) * NNODE + kt + k4];
            As[k4 + 0][row] = v.x; As[k4 + 1][row] = v.y;
            As[k4 + 2][row] = v.z; As[k4 + 3][row] = v.w;
        }
        {
            int krow = tid >> 4, f4 = (tid & 15) * 4;
            float4 v = *(const float4*)&g_A[(rowbase + kt + krow) * KTOT + in_base + n0 + f4];
            *(float4*)&Bs[krow][f4] = v;
        }
        __syncthreads();
#pragma unroll
        for (int kk = 0; kk < BK; kk++) {
            float a[8], b2[4];
#pragma unroll
            for (int i = 0; i < 8; i++) a[i] = As[kk][tm * 8 + i];
#pragma unroll
            for (int j = 0; j < 4; j++) b2[j] = Bs[kk][tn * 4 + j];
#pragma unroll
            for (int i = 0; i < 8; i++)
#pragma unroll
                for (int j = 0; j < 4; j++) acc[i][j] += a[i] * b2[j];
        }
        __syncthreads();
    }
#pragma unroll
    for (int i = 0; i < 8; i++) {
        int m = m0 + tm * 8 + i;
        float4 v = make_float4(acc[i][0], acc[i][1], acc[i][2], acc[i][3]);
        *(float4*)&g_A[(rowbase + m) * KTOT + ob + n0 + tn * 4] = v;
    }
}

// ---------------------------------------------------------------------------
// Gate GEMM: [ROWS x 768] @ Wg[768 x 256] + bg -> sigmoid
// epilogue: o<128: g_rh = r * h ; o>=128: g_u = u
// grid (ROWS/BM, 256/BN)
// ---------------------------------------------------------------------------
__global__ __launch_bounds__(NTHREADS) void gate_kernel(const float* __restrict__ W,
                                                        const float* __restrict__ bias) {
    __shared__ float As[BK][BM + 4];
    __shared__ float Bs[BK][BN];
    const int tid = threadIdx.x;
    const int m0 = blockIdx.x * BM;
    const int o0 = blockIdx.y * BN;
    const int tm = tid >> 4, tn = tid & 15;

    float acc[8][4];
#pragma unroll
    for (int i = 0; i < 8; i++)
#pragma unroll
        for (int j = 0; j < 4; j++) acc[i][j] = 0.f;

    for (int kt = 0; kt < KTOT; kt += BK) {
#pragma unroll
        for (int it = 0; it < 2; it++) {
            int idx = tid + it * NTHREADS;
            int row = idx >> 2, k4 = (idx & 3) * 4;
            float4 v = *(const float4*)&g_A[(size_t)(m0 + row) * KTOT + kt + k4];
            As[k4 + 0][row] = v.x; As[k4 + 1][row] = v.y;
            As[k4 + 2][row] = v.z; As[k4 + 3][row] = v.w;
        }
        {
            int krow = tid >> 4, f4 = (tid & 15) * 4;
            float4 v = *(const float4*)&W[(size_t)(kt + krow) * 256 + o0 + f4];
            *(float4*)&Bs[krow][f4] = v;
        }
        __syncthreads();
#pragma unroll
        for (int kk = 0; kk < BK; kk++) {
            float a[8], b2[4];
#pragma unroll
            for (int i = 0; i < 8; i++) a[i] = As[kk][tm * 8 + i];
#pragma unroll
            for (int j = 0; j < 4; j++) b2[j] = Bs[kk][tn * 4 + j];
#pragma unroll
            for (int i = 0; i < 8; i++)
#pragma unroll
                for (int j = 0; j < 4; j++) acc[i][j] += a[i] * b2[j];
        }
        __syncthreads();
    }

    const int isR = (o0 < 128);
#pragma unroll
    for (int i = 0; i < 8; i++) {
        int row = m0 + tm * 8 + i;
#pragma unroll
        for (int j = 0; j < 4; j++) {
            int o = o0 + tn * 4 + j;
            float g = 1.0f / (1.0f + expf(-(acc[i][j] + bias[o])));
            if (isR) {
                g_rh[(size_t)row * HID + o] = g * g_h[(size_t)row * HID + o];
            } else {
                g_u[(size_t)row * HID + o - 128] = g;
            }
        }
    }
}

// ---------------------------------------------------------------------------
// Candidate GEMM: [ROWS x 768] @ Wc[768 x 128] + bc -> tanh
// epilogue: h = u*h + (1-u)*c ; write g_h and the per-step layer output
// grid (ROWS/BM, 128/BN)
// ---------------------------------------------------------------------------
__global__ __launch_bounds__(NTHREADS) void cand_kernel(const float* __restrict__ W,
                                                        const float* __restrict__ bias,
                                                        float* __restrict__ cur,
                                                        int l, int t) {
    __shared__ float As[BK][BM + 4];
    __shared__ float Bs[BK][BN];
    float* __restrict__ out_t = (l == 0) ? (g_l0out + (size_t)t * BNH)
                                         : (cur + (size_t)t * BNH);
    const int tid = threadIdx.x;
    const int m0 = blockIdx.x * BM;
    const int o0 = blockIdx.y * BN;
    const int tm = tid >> 4, tn = tid & 15;

    float acc[8][4];
#pragma unroll
    for (int i = 0; i < 8; i++)
#pragma unroll
        for (int j = 0; j < 4; j++) acc[i][j] = 0.f;

    for (int kt = 0; kt < KTOT; kt += BK) {
#pragma unroll
        for (int it = 0; it < 2; it++) {
            int idx = tid + it * NTHREADS;
            int row = idx >> 2, k4 = (idx & 3) * 4;
            float4 v = *(const float4*)&g_A[(size_t)(m0 + row) * KTOT + kt + k4];
            As[k4 + 0][row] = v.x; As[k4 + 1][row] = v.y;
            As[k4 + 2][row] = v.z; As[k4 + 3][row] = v.w;
        }
        {
            int krow = tid >> 4, f4 = (tid & 15) * 4;
            float4 v = *(const float4*)&W[(size_t)(kt + krow) * 128 + o0 + f4];
            *(float4*)&Bs[krow][f4] = v;
        }
        __syncthreads();
#pragma unroll
        for (int kk = 0; kk < BK; kk++) {
            float a[8], b2[4];
#pragma unroll
            for (int i = 0; i < 8; i++) a[i] = As[kk][tm * 8 + i];
#pragma unroll
            for (int j = 0; j < 4; j++) b2[j] = Bs[kk][tn * 4 + j];
#pragma unroll
            for (int i = 0; i < 8; i++)
#pragma unroll
                for (int j = 0; j < 4; j++) acc[i][j] += a[i] * b2[j];
        }
        __syncthreads();
    }

#pragma unroll
    for (int i = 0; i < 8; i++) {
        int row = m0 + tm * 8 + i;
#pragma unroll
        for (int j = 0; j < 4; j++) {
            int o = o0 + tn * 4 + j;
            float c = tanhf(acc[i][j] + bias[o]);
            size_t idx = (size_t)row * HID + o;
            float u = g_u[idx];
            float hn = u * g_h[idx] + (1.0f - u) * c;
            g_h[idx] = hn;
            out_t[idx] = hn;
        }
    }
}

// ---------------------------------------------------------------------------
// Small elementwise kernels (all float4, 2048 blocks x 256 threads)
// ---------------------------------------------------------------------------
__global__ void pack_xh(const float* __restrict__ inputs, int l, int t) {
    const float* __restrict__ x = (l == 0) ? inputs + (size_t)t * BNH
                                           : g_l0out + (size_t)t * BNH;
    int i = blockIdx.x * blockDim.x + threadIdx.x;  // one float4 per half
    int r = i >> 5;
    int c = (i & 31) * 4;
    float4 xv = *(const float4*)&x[(size_t)r * DIN + c];
    float4 hv = *(const float4*)&g_h[(size_t)r * HID + c];
    *(float4*)&g_A[(size_t)r * KTOT + c] = xv;
    *(float4*)&g_A[(size_t)r * KTOT + 128 + c] = hv;
}

__global__ void pack_rh() {
    int i = blockIdx.x * blockDim.x + threadIdx.x;
    int r = i >> 5;
    int c = (i & 31) * 4;
    *(float4*)&g_A[(size_t)r * KTOT + 128 + c] = *(const float4*)&g_rh[(size_t)r * HID + c];
}

__global__ void copy_hinit(const float* __restrict__ ihs, int l) {
    int i = (blockIdx.x * blockDim.x + threadIdx.x) * 4;
    *(float4*)&g_h[i] = *(const float4*)&ihs[(size_t)l * BNH + i];
}

__global__ void copy_final(float* __restrict__ out, int l) {
    int i = (blockIdx.x * blockDim.x + threadIdx.x) * 4;
    *(float4*)&out[(size_t)l * BNH + i] = *(const float4*)&g_h[i];
}

// ---------------------------------------------------------------------------
extern "C" void kernel_launch(void* const* d_in, const int* in_sizes, int n_in,
                              void* d_out, int out_size) {
    const float* inputs = (const float*)d_in[0];  // [T,B,N,D]
    const float* ihs    = (const float*)d_in[1];  // [L,B,N,H]
    const float* S      = (const float*)d_in[2];  // [1,N,N]
    const float* Wg     = (const float*)d_in[3];  // [L,768,256]
    const float* bg     = (const float*)d_in[4];  // [L,256]
    const float* Wc     = (const float*)d_in[5];  // [L,768,128]
    const float* bc     = (const float*)d_in[6];  // [L,128]
    float* out = (float*)d_out;
    float* cur = out + FINALS;                    // [T,B,N,H] region

    m2_kernel<<<dim3(4, 8), NTHREADS>>>(S);

    for (int l = 0; l < 2; l++) {
        copy_hinit<<<BNH / (4 * 256), 256>>>(ihs, l);
        for (int t = 0; t < TS; t++) {
            // cols 0..127 = x_t, 128..255 = h
            pack_xh<<<ROWS * 32 / 256, 256>>>(inputs, l, t);
            // d1 = S@[x|h] -> cols 256..511 ; d2 = M2@[x|h] -> cols 512..767
            diff_kernel<<<dim3(NNODE / BM, 256 / BN, 2 * BB), NTHREADS>>>(S, 0, 256, 512);
            // gates: produce u and r*h
            gate_kernel<<<dim3(ROWS / BM, 256 / BN), NTHREADS>>>(
                Wg + (size_t)l * KTOT * 256, bg + (size_t)l * 256);
            // cols 128..255 = r*h  (x-half diffusion in cols 256..383 / 512..639 reused)
            pack_rh<<<ROWS * 32 / 256, 256>>>();
            // re-diffuse only the rh half -> cols 384..511 and 640..767
            diff_kernel<<<dim3(NNODE / BM, 128 / BN, 2 * BB), NTHREADS>>>(S, 128, 384, 640);
            // candidate + GRU update, writes h and per-step output
            cand_kernel<<<dim3(ROWS / BM, 128 / BN), NTHREADS>>>(
                Wc + (size_t)l * KTOT * 128, bc + (size_t)l * 128, cur, l, t);
        }
        copy_final<<<BNH / (4 * 256), 256>>>(out, l);
    }
}

// round 5
// speedup vs baseline: 6.3194x; 6.3194x over previous
#include <cuda_runtime.h>
#include <cuda_fp16.h>
#include <cstdint>
#include <math.h>

// Problem constants
#define TS     32
#define BB     32
#define NNODE  512
#define DIN    128
#define HID    128
#define KTOT   768
#define ROWS   (BB * NNODE)        // 16384
#define BNH    (BB * NNODE * HID)  // 2097152
#define FINALS (2 * BNH)

#define BKC 32                     // K chunk (halfs)
#define LDS 40                     // smem row pitch (halfs), padded

// ---------------------------------------------------------------------------
// Device scratch (allocation-free)
// ---------------------------------------------------------------------------
__device__ float  g_M2[NNODE * NNODE];
__device__ __half g_S16[NNODE * NNODE];
__device__ __half g_M216[NNODE * NNODE];
__device__ __half g_A16[(size_t)ROWS * KTOT];            // [x|h/rh|d1|d2] fp16
__device__ __half g_CT16[(size_t)BB * 256 * NNODE];      // [x|h]^T per batch
__device__ __half g_RT16[(size_t)BB * 128 * NNODE];      // rh^T per batch
__device__ float  g_h[BNH];
__device__ float  g_u[BNH];
__device__ float  g_l0out[(size_t)TS * BNH];
__device__ __half g_WgT[2 * 256 * KTOT];                 // [l][o][k]
__device__ __half g_WcT[2 * 128 * KTOT];

// ---------------------------------------------------------------------------
// PTX helpers (arch-generic: cp.async / ldmatrix / mma.sync)
// ---------------------------------------------------------------------------
__device__ __forceinline__ uint32_t smem_u32(const void* p) {
    return (uint32_t)__cvta_generic_to_shared(p);
}
__device__ __forceinline__ void cp_async16(uint32_t saddr, const void* g) {
    asm volatile("cp.async.cg.shared.global [%0], [%1], 16;" :: "r"(saddr), "l"(g));
}
#define CP_COMMIT() asm volatile("cp.async.commit_group;" ::: "memory")
#define CP_WAIT(N)  asm volatile("cp.async.wait_group %0;" :: "n"(N) : "memory")

__device__ __forceinline__ void ldm_x4(uint32_t& r0, uint32_t& r1, uint32_t& r2,
                                       uint32_t& r3, uint32_t a) {
    asm volatile("ldmatrix.sync.aligned.m8n8.x4.shared.b16 {%0,%1,%2,%3}, [%4];"
                 : "=r"(r0), "=r"(r1), "=r"(r2), "=r"(r3) : "r"(a));
}
__device__ __forceinline__ void mma16816(float* d, const uint32_t* a, const uint32_t* b) {
    asm volatile("mma.sync.aligned.m16n8k16.row.col.f32.f16.f16.f32 "
                 "{%0,%1,%2,%3}, {%4,%5,%6,%7}, {%8,%9}, {%0,%1,%2,%3};"
                 : "+f"(d[0]), "+f"(d[1]), "+f"(d[2]), "+f"(d[3])
                 : "r"(a[0]), "r"(a[1]), "r"(a[2]), "r"(a[3]), "r"(b[0]), "r"(b[1]));
}

// ---------------------------------------------------------------------------
// Shared mainloop: acc[128x128] += A[128 x K] @ B[128 x K]^T, K = NCH*32.
// A, B fp16 row-major (K contiguous). cp.async double-buffered.
// Block: 256 threads = 8 warps (2x4 warp grid, 64x32 warp tiles).
// ---------------------------------------------------------------------------
template<int NCH>
__device__ __forceinline__ void mma_mainloop(
    const __half* __restrict__ A, int lda,
    const __half* __restrict__ B, int ldb,
    __half (*sA)[128][LDS], __half (*sB)[128][LDS],
    float acc[16][4])
{
    const int tid = threadIdx.x;
    const int lane = tid & 31, warp = tid >> 5;
    const int wm = warp >> 2, wn = warp & 3;

#pragma unroll
    for (int i = 0; i < 16; i++)
#pragma unroll
        for (int j = 0; j < 4; j++) acc[i][j] = 0.f;

    auto load_chunk = [&](int c, int buf) {
        const int k0 = c * BKC;
#pragma unroll
        for (int i = 0; i < 2; i++) {
            int idx = i * 256 + tid;
            int row = idx >> 2, cg = idx & 3;
            cp_async16(smem_u32(&sA[buf][row][cg * 8]),
                       A + (size_t)row * lda + k0 + cg * 8);
        }
#pragma unroll
        for (int i = 0; i < 2; i++) {
            int idx = i * 256 + tid;
            int row = idx >> 2, cg = idx & 3;
            cp_async16(smem_u32(&sB[buf][row][cg * 8]),
                       B + (size_t)row * ldb + k0 + cg * 8);
        }
        CP_COMMIT();
    };

    load_chunk(0, 0);

    for (int c = 0; c < NCH; c++) {
        if (c + 1 < NCH) { load_chunk(c + 1, (c + 1) & 1); CP_WAIT(1); }
        else             { CP_WAIT(0); }
        __syncthreads();
        const int buf = c & 1;
#pragma unroll
        for (int kk = 0; kk < BKC; kk += 16) {
            uint32_t af[4][4], bf[4][2];
#pragma unroll
            for (int mt = 0; mt < 4; mt++) {
                uint32_t ad = smem_u32(&sA[buf][wm * 64 + mt * 16 + (lane & 15)]
                                          [kk + (lane >> 4) * 8]);
                ldm_x4(af[mt][0], af[mt][1], af[mt][2], af[mt][3], ad);
            }
#pragma unroll
            for (int nt2 = 0; nt2 < 2; nt2++) {
                uint32_t bd = smem_u32(&sB[buf][wn * 32 + nt2 * 16 + (lane & 15)]
                                          [kk + (lane >> 4) * 8]);
                uint32_t r0, r1, r2, r3;
                ldm_x4(r0, r1, r2, r3, bd);
                bf[nt2 * 2 + 0][0] = r0; bf[nt2 * 2 + 0][1] = r2;
                bf[nt2 * 2 + 1][0] = r1; bf[nt2 * 2 + 1][1] = r3;
            }
#pragma unroll
            for (int mt = 0; mt < 4; mt++)
#pragma unroll
                for (int nt = 0; nt < 4; nt++)
                    mma16816(acc[mt * 4 + nt], af[mt], bf[nt]);
        }
        __syncthreads();
    }
}

// acc element mapping helpers (m16n8k16 accumulator layout):
// d0 -> (r = lane/4, c = (lane%4)*2), d1 -> c+1, d2/d3 -> r+8.

// ---------------------------------------------------------------------------
// Diffusion GEMM: out[b, m, cb+f] = sum_n Mat[m,n] * catT[b, f, n]
// grid (4 m-blocks, NN/128 f-blocks, 64: z = b*2 + mat)
// ---------------------------------------------------------------------------
template<int NN>
__global__ __launch_bounds__(256) void diff_tc(int cbS, int cbM2) {
    __shared__ __half sA[2][128][LDS];
    __shared__ __half sB[2][128][LDS];
    const int m0 = blockIdx.x * 128;
    const int nb = blockIdx.y;
    const int b = blockIdx.z >> 1, mat = blockIdx.z & 1;

    const __half* A = (mat ? g_M216 : g_S16) + (size_t)m0 * NNODE;
    const __half* Bp = ((NN == 256) ? (g_CT16 + (size_t)b * 256 * NNODE)
                                    : (g_RT16 + (size_t)b * 128 * NNODE))
                       + (size_t)nb * 128 * NNODE;
    float acc[16][4];
    mma_mainloop<16>(A, NNODE, Bp, NNODE, sA, sB, acc);

    const int lane = threadIdx.x & 31, warp = threadIdx.x >> 5;
    const int wm = warp >> 2, wn = warp & 3;
    const int cb = (mat ? cbM2 : cbS) + nb * 128;
#pragma unroll
    for (int mt = 0; mt < 4; mt++) {
        const size_t row0 = (size_t)b * NNODE + m0 + wm * 64 + mt * 16 + (lane >> 2);
#pragma unroll
        for (int nt = 0; nt < 4; nt++) {
            const int c = cb + wn * 32 + nt * 8 + (lane & 3) * 2;
            const float* d = acc[mt * 4 + nt];
            __half2 lo = __floats2half2_rn(d[0], d[1]);
            __half2 hi = __floats2half2_rn(d[2], d[3]);
            *(__half2*)&g_A16[row0 * KTOT + c] = lo;
            *(__half2*)&g_A16[(row0 + 8) * KTOT + c] = hi;
        }
    }
}

// ---------------------------------------------------------------------------
// Gate GEMM: [ROWS x 768] @ WgT[l][256 x 768]^T, sigmoid.
// grid (128 m-blocks, 2 o-blocks). y==0 -> r path (rh), y==1 -> u path.
// ---------------------------------------------------------------------------
__global__ __launch_bounds__(256) void gate_tc(const float* __restrict__ bias, int l) {
    __shared__ __half sA[2][128][LDS];
    __shared__ __half sB[2][128][LDS];
    const int m0 = blockIdx.x * 128;
    const int o0 = blockIdx.y * 128;

    const __half* A = g_A16 + (size_t)m0 * KTOT;
    const __half* Bp = g_WgT + (size_t)l * 256 * KTOT + (size_t)o0 * KTOT;
    float acc[16][4];
    mma_mainloop<24>(A, KTOT, Bp, KTOT, sA, sB, acc);

    const int lane = threadIdx.x & 31, warp = threadIdx.x >> 5;
    const int wm = warp >> 2, wn = warp & 3;
    const int rpath = (blockIdx.y == 0);
#pragma unroll
    for (int mt = 0; mt < 4; mt++) {
#pragma unroll
        for (int half = 0; half < 2; half++) {
            const size_t row = (size_t)m0 + wm * 64 + mt * 16 + (lane >> 2) + half * 8;
            const int bidx = (int)(row >> 9);
            const int node = (int)(row & 511);
#pragma unroll
            for (int nt = 0; nt < 4; nt++) {
                const int o = o0 + wn * 32 + nt * 8 + (lane & 3) * 2;
                const float* d = acc[mt * 4 + nt] + half * 2;
                float g0 = 1.0f / (1.0f + expf(-(d[0] + bias[o])));
                float g1 = 1.0f / (1.0f + expf(-(d[1] + bias[o + 1])));
                if (rpath) {
                    float rh0 = g0 * g_h[row * HID + o];
                    float rh1 = g1 * g_h[row * HID + o + 1];
                    __half h0 = __float2half(rh0), h1 = __float2half(rh1);
                    *(__half2*)&g_A16[row * KTOT + 128 + o] = __halves2half2(h0, h1);
                    g_RT16[((size_t)bidx * 128 + o) * NNODE + node] = h0;
                    g_RT16[((size_t)bidx * 128 + o + 1) * NNODE + node] = h1;
                } else {
                    *(float2*)&g_u[row * HID + (o - 128)] = make_float2(g0, g1);
                }
            }
        }
    }
}

// ---------------------------------------------------------------------------
// Candidate GEMM: [ROWS x 768] @ WcT[l][128 x 768]^T, tanh + GRU update.
// grid (128 m-blocks).
// ---------------------------------------------------------------------------
__global__ __launch_bounds__(256) void cand_tc(const float* __restrict__ bias, int l, int t,
                                               float* __restrict__ cur) {
    __shared__ __half sA[2][128][LDS];
    __shared__ __half sB[2][128][LDS];
    const int m0 = blockIdx.x * 128;

    const __half* A = g_A16 + (size_t)m0 * KTOT;
    const __half* Bp = g_WcT + (size_t)l * 128 * KTOT;
    float acc[16][4];
    mma_mainloop<24>(A, KTOT, Bp, KTOT, sA, sB, acc);

    float* __restrict__ outp = (l == 0) ? (g_l0out + (size_t)t * BNH)
                                        : (cur + (size_t)t * BNH);
    const int lane = threadIdx.x & 31, warp = threadIdx.x >> 5;
    const int wm = warp >> 2, wn = warp & 3;
#pragma unroll
    for (int mt = 0; mt < 4; mt++) {
#pragma unroll
        for (int half = 0; half < 2; half++) {
            const size_t row = (size_t)m0 + wm * 64 + mt * 16 + (lane >> 2) + half * 8;
#pragma unroll
            for (int nt = 0; nt < 4; nt++) {
                const int o = wn * 32 + nt * 8 + (lane & 3) * 2;
                const float* d = acc[mt * 4 + nt] + half * 2;
                const size_t idx = row * HID + o;
                float c0 = tanhf(d[0] + bias[o]);
                float c1 = tanhf(d[1] + bias[o + 1]);
                float u0 = g_u[idx], u1 = g_u[idx + 1];
                float h0 = u0 * g_h[idx] + (1.0f - u0) * c0;
                float h1 = u1 * g_h[idx + 1] + (1.0f - u1) * c1;
                float2 hv = make_float2(h0, h1);
                *(float2*)&g_h[idx] = hv;
                *(float2*)&outp[idx] = hv;
            }
        }
    }
}

// ---------------------------------------------------------------------------
// pack1: A16 cols 0-255 = fp16([x|h]) and CT16 = [x|h]^T (per batch)
// ---------------------------------------------------------------------------
__global__ __launch_bounds__(256) void pack1(const float* __restrict__ inputs, int l, int t) {
    __shared__ __half sm[128][136];
    const int blk = blockIdx.x;
    const size_t r0 = (size_t)blk * 128;
    const int b = blk >> 2;
    const int n0 = (blk & 3) * 128;
    const float* __restrict__ xsrc = (l == 0) ? (inputs + (size_t)t * ROWS * DIN)
                                              : (g_l0out + (size_t)t * BNH);
    const int tid = threadIdx.x;
    for (int it = 0; it < 64; it++) {
        int idx = it * 256 + tid;
        int rr = idx >> 7, cc = idx & 127;
        __half hv = __float2half(xsrc[(r0 + rr) * DIN + cc]);
        sm[rr][cc] = hv;
        g_A16[(r0 + rr) * KTOT + cc] = hv;
    }
    __syncthreads();
    for (int it = 0; it < 64; it++) {
        int idx = it * 256 + tid;
        int f = idx >> 7, n = idx & 127;
        g_CT16[((size_t)b * 256 + f) * NNODE + n0 + n] = sm[n][f];
    }
    __syncthreads();
    for (int it = 0; it < 64; it++) {
        int idx = it * 256 + tid;
        int rr = idx >> 7, cc = idx & 127;
        __half hv = __float2half(g_h[(r0 + rr) * HID + cc]);
        sm[rr][cc] = hv;
        g_A16[(r0 + rr) * KTOT + 128 + cc] = hv;
    }
    __syncthreads();
    for (int it = 0; it < 64; it++) {
        int idx = it * 256 + tid;
        int f = idx >> 7, n = idx & 127;
        g_CT16[((size_t)b * 256 + 128 + f) * NNODE + n0 + n] = sm[n][f];
    }
}

// ---------------------------------------------------------------------------
// M2 = 2*S@S - I (fp32 SIMT, once) + converts + weight transposes
// ---------------------------------------------------------------------------
__global__ __launch_bounds__(256) void m2_kernel(const float* __restrict__ S) {
    __shared__ float As[16][132];
    __shared__ float Bs[16][64];
    const int tid = threadIdx.x;
    const int m0 = blockIdx.x * 128, n0 = blockIdx.y * 64;
    const int tm = tid >> 4, tn = tid & 15;
    float acc[8][4];
#pragma unroll
    for (int i = 0; i < 8; i++)
#pragma unroll
        for (int j = 0; j < 4; j++) acc[i][j] = 0.f;
    for (int kt = 0; kt < NNODE; kt += 16) {
#pragma unroll
        for (int it = 0; it < 2; it++) {
            int idx = tid + it * 256;
            int row = idx >> 2, k4 = (idx & 3) * 4;
            float4 v = *(const float4*)&S[(size_t)(m0 + row) * NNODE + kt + k4];
            As[k4 + 0][row] = v.x; As[k4 + 1][row] = v.y;
            As[k4 + 2][row] = v.z; As[k4 + 3][row] = v.w;
        }
        {
            int krow = tid >> 4, f4 = (tid & 15) * 4;
            float4 v = *(const float4*)&S[(size_t)(kt + krow) * NNODE + n0 + f4];
            *(float4*)&Bs[krow][f4] = v;
        }
        __syncthreads();
#pragma unroll
        for (int kk = 0; kk < 16; kk++) {
            float a[8], bb[4];
#pragma unroll
            for (int i = 0; i < 8; i++) a[i] = As[kk][tm * 8 + i];
#pragma unroll
            for (int j = 0; j < 4; j++) bb[j] = Bs[kk][tn * 4 + j];
#pragma unroll
            for (int i = 0; i < 8; i++)
#pragma unroll
                for (int j = 0; j < 4; j++) acc[i][j] += a[i] * bb[j];
        }
        __syncthreads();
    }
#pragma unroll
    for (int i = 0; i < 8; i++) {
        int m = m0 + tm * 8 + i;
#pragma unroll
        for (int j = 0; j < 4; j++) {
            int n = n0 + tn * 4 + j;
            g_M2[(size_t)m * NNODE + n] = 2.0f * acc[i][j] - (m == n ? 1.0f : 0.0f);
        }
    }
}

__global__ void conv_mats(const float* __restrict__ S) {
    int i = blockIdx.x * 256 + threadIdx.x;
    g_S16[i] = __float2half(S[i]);
    g_M216[i] = __float2half(g_M2[i]);
}

__global__ void wtrans(const float* __restrict__ Wg, const float* __restrict__ Wc) {
    int i = blockIdx.x * 256 + threadIdx.x;
    if (i < 2 * 256 * KTOT) {
        int l = i / (256 * KTOT), rem = i % (256 * KTOT);
        int o = rem / KTOT, k = rem % KTOT;
        g_WgT[i] = __float2half(Wg[(size_t)l * KTOT * 256 + (size_t)k * 256 + o]);
    }
    if (i < 2 * 128 * KTOT) {
        int l = i / (128 * KTOT), rem = i % (128 * KTOT);
        int o = rem / KTOT, k = rem % KTOT;
        g_WcT[i] = __float2half(Wc[(size_t)l * KTOT * 128 + (size_t)k * 128 + o]);
    }
}

__global__ void init_h(const float* __restrict__ ihs, int l) {
    int i = (blockIdx.x * blockDim.x + threadIdx.x) * 4;
    *(float4*)&g_h[i] = *(const float4*)&ihs[(size_t)l * BNH + i];
}
__global__ void copy_final(float* __restrict__ out, int l) {
    int i = (blockIdx.x * blockDim.x + threadIdx.x) * 4;
    *(float4*)&out[(size_t)l * BNH + i] = *(const float4*)&g_h[i];
}

// ---------------------------------------------------------------------------
extern "C" void kernel_launch(void* const* d_in, const int* in_sizes, int n_in,
                              void* d_out, int out_size) {
    const float* inputs = (const float*)d_in[0];
    const float* ihs    = (const float*)d_in[1];
    const float* S      = (const float*)d_in[2];
    const float* Wg     = (const float*)d_in[3];
    const float* bg     = (const float*)d_in[4];
    const float* Wc     = (const float*)d_in[5];
    const float* bc     = (const float*)d_in[6];
    float* out = (float*)d_out;
    float* cur = out + FINALS;

    m2_kernel<<<dim3(4, 8), 256>>>(S);
    conv_mats<<<1024, 256>>>(S);
    wtrans<<<1536, 256>>>(Wg, Wc);

    for (int l = 0; l < 2; l++) {
        init_h<<<2048, 256>>>(ihs, l);
        for (int t = 0; t < TS; t++) {
            pack1<<<128, 256>>>(inputs, l, t);
            // S@[x|h] -> cols 256..511 ; M2@[x|h] -> cols 512..767
            diff_tc<256><<<dim3(4, 2, 64), 256>>>(256, 512);
            gate_tc<<<dim3(128, 2), 256>>>(bg + (size_t)l * 256, l);
            // S@rh -> cols 384..511 ; M2@rh -> cols 640..767
            diff_tc<128><<<dim3(4, 1, 64), 256>>>(384, 640);
            cand_tc<<<128, 256>>>(bc + (size_t)l * 128, l, t, cur);
        }
        copy_final<<<2048, 256>>>(out, l);
    }
}

// round 15
// speedup vs baseline: 6.8886x; 1.0901x over previous
#include <cuda_runtime.h>
#include <cuda_fp16.h>
#include <cstdint>
#include <math.h>

// Problem constants
#define TS     32
#define BB     32
#define NNODE  512
#define DIN    128
#define HID    128
#define KTOT   768
#define ROWS   (BB * NNODE)        // 16384
#define BNH    (BB * NNODE * HID)  // 2097152
#define FINALS (2 * BNH)

// ---------------------------------------------------------------------------
// Device scratch (allocation-free)
// ---------------------------------------------------------------------------
__device__ float  g_M2[NNODE * NNODE];
__device__ __half g_S16[NNODE * NNODE];
__device__ __half g_M216[NNODE * NNODE];
__device__ __half g_X16[(size_t)TS * ROWS * DIN];        // layer-0 x fp16 (natural)
__device__ __half g_l0out[(size_t)TS * ROWS * HID];      // layer-0 outputs fp16
__device__ __half g_XPRE[(size_t)TS * ROWS * 256];       // [Sx | M2x] per t
__device__ __half g_XT[(size_t)TS * BB * 128 * NNODE];   // x^T per (t,b): [feat][node]
__device__ __half g_HT[(size_t)BB * 128 * NNODE];        // h^T per b
__device__ __half g_RT[(size_t)BB * 128 * NNODE];        // rh^T per b
__device__ __half g_dyn1[(size_t)ROWS * 384];            // [h  | Sh  | M2h ]
__device__ __half g_dyn2[(size_t)ROWS * 384];            // [rh | Srh | M2rh]
__device__ float  g_h[BNH];
__device__ float  g_u[BNH];
__device__ __half g_WgPT[2 * 256 * KTOT];                // [l][o][kp] permuted
__device__ __half g_WcPT[2 * 128 * KTOT];

// ---------------------------------------------------------------------------
// PTX helpers (arch-generic: cp.async / ldmatrix / mma.sync)
// ---------------------------------------------------------------------------
__device__ __forceinline__ uint32_t smem_u32(const void* p) {
    return (uint32_t)__cvta_generic_to_shared(p);
}
__device__ __forceinline__ void cp_async16(uint32_t saddr, const void* g) {
    asm volatile("cp.async.cg.shared.global [%0], [%1], 16;" :: "r"(saddr), "l"(g));
}
#define CP_COMMIT() asm volatile("cp.async.commit_group;" ::: "memory")
#define CP_WAIT(N)  asm volatile("cp.async.wait_group %0;" :: "n"(N) : "memory")

__device__ __forceinline__ void ldm_x4(uint32_t& r0, uint32_t& r1, uint32_t& r2,
                                       uint32_t& r3, uint32_t a) {
    asm volatile("ldmatrix.sync.aligned.m8n8.x4.shared.b16 {%0,%1,%2,%3}, [%4];"
                 : "=r"(r0), "=r"(r1), "=r"(r2), "=r"(r3) : "r"(a));
}
__device__ __forceinline__ void mma16816(float* d, const uint32_t* a, const uint32_t* b) {
    asm volatile("mma.sync.aligned.m16n8k16.row.col.f32.f16.f16.f32 "
                 "{%0,%1,%2,%3}, {%4,%5,%6,%7}, {%8,%9}, {%0,%1,%2,%3};"
                 : "+f"(d[0]), "+f"(d[1]), "+f"(d[2]), "+f"(d[3])
                 : "r"(a[0]), "r"(a[1]), "r"(a[2]), "r"(a[3]), "r"(b[0]), "r"(b[1]));
}

// ---------------------------------------------------------------------------
// 3-stage pipelined mainloop (non-trans ldmatrix only).
// C[128 x NT*8*4 cols] = A[128 x K] @ B[NROWS x K]^T.
// A fp16 row-major, up to 3 K-regions (rb0/rb1 chunk bounds).
// B row-major [ocol][k] (weights or feat-major transposed activations).
// Block: 256 threads, warps 2(m) x 4(n); warp tile 64 x (NT*8).
// ---------------------------------------------------------------------------
template<int NCH, int NT>
__device__ __forceinline__ void mainloop3(
    const __half* A0, int lda0, const __half* A1, int lda1,
    const __half* A2, int lda2, int rb0, int rb1,
    const __half* B, int ldb,
    __half* sm, float (*acc)[4])
{
    constexpr int NROWS = NT * 32;       // B rows (128 or 64)
    constexpr int A_STAGE = 128 * 40;
    constexpr int B_STAGE = NROWS * 40;
    constexpr int WN = NT * 8;
    __half* sA = sm;
    __half* sB = sm + 3 * A_STAGE;

    const int tid = threadIdx.x, lane = tid & 31, warp = tid >> 5;
    const int wm = warp >> 2, wn = warp & 3;

#pragma unroll
    for (int i = 0; i < 4 * NT; i++)
#pragma unroll
        for (int j = 0; j < 4; j++) acc[i][j] = 0.f;

    auto load = [&](int c, int s) {
        const __half* P; int ld, k0;
        if (c < rb0)      { P = A0; ld = lda0; k0 = c * 32; }
        else if (c < rb1) { P = A1; ld = lda1; k0 = (c - rb0) * 32; }
        else              { P = A2; ld = lda2; k0 = (c - rb1) * 32; }
        __half* sa = sA + s * A_STAGE;
#pragma unroll
        for (int i = 0; i < 2; i++) {
            int idx = i * 256 + tid;
            int r = idx >> 2, cg = idx & 3;
            cp_async16(smem_u32(sa + r * 40 + cg * 8), P + (size_t)r * ld + k0 + cg * 8);
        }
        __half* sb = sB + s * B_STAGE;
#pragma unroll
        for (int i = 0; i < NROWS / 64; i++) {
            int idx = i * 256 + tid;
            int r = idx >> 2, cg = idx & 3;
            cp_async16(smem_u32(sb + r * 40 + cg * 8),
                       B + (size_t)r * ldb + c * 32 + cg * 8);
        }
        CP_COMMIT();
    };

    load(0, 0);
    load(1, 1);

    for (int c = 0; c < NCH; c++) {
        const int s = c % 3;
        if (c + 1 < NCH) { CP_WAIT(1); }
        else             { CP_WAIT(0); }
        __syncthreads();
        if (c + 2 < NCH) load(c + 2, (c + 2) % 3);
        __half* sa = sA + s * A_STAGE;
        __half* sb = sB + s * B_STAGE;
#pragma unroll
        for (int kk = 0; kk < 32; kk += 16) {
            uint32_t af[4][4];
#pragma unroll
            for (int mt = 0; mt < 4; mt++) {
                uint32_t ad = smem_u32(sa + (wm * 64 + mt * 16 + (lane & 15)) * 40
                                          + kk + (lane >> 4) * 8);
                ldm_x4(af[mt][0], af[mt][1], af[mt][2], af[mt][3], ad);
            }
            uint32_t bf[NT][2];
#pragma unroll
            for (int n2 = 0; n2 < NT / 2; n2++) {
                uint32_t r0, r1, r2, r3;
                uint32_t bd = smem_u32(sb + (wn * WN + n2 * 16 + (lane & 15)) * 40
                                          + kk + (lane >> 4) * 8);
                ldm_x4(r0, r1, r2, r3, bd);
                bf[n2 * 2][0] = r0;     bf[n2 * 2][1] = r2;
                bf[n2 * 2 + 1][0] = r1; bf[n2 * 2 + 1][1] = r3;
            }
#pragma unroll
            for (int mt = 0; mt < 4; mt++)
#pragma unroll
                for (int nt = 0; nt < NT; nt++)
                    mma16816(acc[mt * NT + nt], af[mt], bf[nt]);
        }
    }
}

#define SMEM_DIFF  ((3 * 128 * 40 + 3 * 128 * 40) * 2)   // 61440 B
#define SMEM_GATE  ((3 * 128 * 40 + 3 * 128 * 40) * 2)   // 61440 B
#define SMEM_CAND  ((3 * 128 * 40 + 3 * 64 * 40) * 2)    // 46080 B

// x-source select in device code
__device__ __forceinline__ const __half* xsrc_dev(int l) {
    return (l == 0) ? g_X16 : g_l0out;
}

// ---------------------------------------------------------------------------
// Per-step diffusion: out[b,m,f] = Mat @ BT[b]  (BT = h^T or rh^T, [feat][node])
// which==0: BT=g_HT, out=g_dyn1+128 ; which==1: BT=g_RT, out=g_dyn2+128.
// ALL buffer pointers resolved in DEVICE code — __device__ symbols must
// never be passed as kernel arguments from host (host sees the shadow;
// on GB300 ATS makes that dereference silently read host RAM).
// grid (4, 1, 64): z = b*2 + mat. Writes cols mat*128 + f.
// ---------------------------------------------------------------------------
__global__ __launch_bounds__(256) void diff_step(int which) {
    extern __shared__ __half sm[];
    const int m0 = blockIdx.x * 128;
    const int b = blockIdx.z >> 1, mat = blockIdx.z & 1;
    const __half* BT = which ? g_RT : g_HT;
    __half* outb = (which ? g_dyn2 : g_dyn1) + 128;
    const __half* A = (mat ? g_M216 : g_S16) + (size_t)m0 * NNODE;
    const __half* B = BT + (size_t)b * 128 * NNODE;
    float acc[16][4];
    mainloop3<16, 4>(A, NNODE, A, NNODE, A, NNODE, 16, 16, B, NNODE, sm, acc);

    const int lane = threadIdx.x & 31, warp = threadIdx.x >> 5;
    const int wm = warp >> 2, wn = warp & 3;
#pragma unroll
    for (int mt = 0; mt < 4; mt++) {
        const size_t row0 = (size_t)b * NNODE + m0 + wm * 64 + mt * 16 + (lane >> 2);
#pragma unroll
        for (int nt = 0; nt < 4; nt++) {
            const int f = mat * 128 + wn * 32 + nt * 8 + (lane & 3) * 2;
            const float* d = acc[mt * 4 + nt];
            *(__half2*)&outb[row0 * 384 + f] = __floats2half2_rn(d[0], d[1]);
            *(__half2*)&outb[(row0 + 8) * 384 + f] = __floats2half2_rn(d[2], d[3]);
        }
    }
}

// ---------------------------------------------------------------------------
// Batched x-diffusion for ALL t: XPRE[t] = [S@x_t | M2@x_t]. grid (4, 32, 64).
// B = g_XT (x^T per (t,b)), resolved device-side.
// ---------------------------------------------------------------------------
__global__ __launch_bounds__(256) void bigdiff() {
    extern __shared__ __half sm[];
    const int m0 = blockIdx.x * 128, t = blockIdx.y;
    const int b = blockIdx.z >> 1, mat = blockIdx.z & 1;
    const __half* A = (mat ? g_M216 : g_S16) + (size_t)m0 * NNODE;
    const __half* B = g_XT + ((size_t)t * BB + b) * (128 * NNODE);
    float acc[16][4];
    mainloop3<16, 4>(A, NNODE, A, NNODE, A, NNODE, 16, 16, B, NNODE, sm, acc);

    const int lane = threadIdx.x & 31, warp = threadIdx.x >> 5;
    const int wm = warp >> 2, wn = warp & 3;
    __half* outb = g_XPRE + (size_t)t * ROWS * 256;
#pragma unroll
    for (int mt = 0; mt < 4; mt++) {
        const size_t row0 = (size_t)b * NNODE + m0 + wm * 64 + mt * 16 + (lane >> 2);
#pragma unroll
        for (int nt = 0; nt < 4; nt++) {
            const int f = mat * 128 + wn * 32 + nt * 8 + (lane & 3) * 2;
            const float* d = acc[mt * 4 + nt];
            *(__half2*)&outb[row0 * 256 + f] = __floats2half2_rn(d[0], d[1]);
            *(__half2*)&outb[(row0 + 8) * 256 + f] = __floats2half2_rn(d[2], d[3]);
        }
    }
}

// ---------------------------------------------------------------------------
// Gate GEMM (K=768 over 3 regions), sigmoid. grid(128, 2).
// o<128: rh -> dyn2 cols 0..127 + g_RT (rh^T). o>=128: u -> g_u (fp32).
// ---------------------------------------------------------------------------
__global__ __launch_bounds__(256) void gate_tc(const float* __restrict__ bias,
                                               int t, int l) {
    extern __shared__ __half sm[];
    const int m0 = blockIdx.x * 128, o0 = blockIdx.y * 128;
    const __half* A0 = xsrc_dev(l) + ((size_t)t * ROWS + m0) * DIN;
    const __half* A1 = g_XPRE + ((size_t)t * ROWS + m0) * 256;
    const __half* A2 = g_dyn1 + (size_t)m0 * 384;
    const __half* B = g_WgPT + (size_t)l * 256 * KTOT + (size_t)o0 * KTOT;
    float acc[16][4];
    mainloop3<24, 4>(A0, DIN, A1, 256, A2, 384, 4, 12, B, KTOT, sm, acc);

    const int lane = threadIdx.x & 31, warp = threadIdx.x >> 5;
    const int wm = warp >> 2, wn = warp & 3;
    const int rpath = (o0 == 0);
#pragma unroll
    for (int mt = 0; mt < 4; mt++) {
#pragma unroll
        for (int half = 0; half < 2; half++) {
            const size_t row = (size_t)m0 + wm * 64 + mt * 16 + (lane >> 2) + half * 8;
            const int bidx = (int)(row >> 9);
            const int node = (int)(row & 511);
#pragma unroll
            for (int nt = 0; nt < 4; nt++) {
                const int o = o0 + wn * 32 + nt * 8 + (lane & 3) * 2;
                const float* d = acc[mt * 4 + nt] + half * 2;
                float g0 = 1.0f / (1.0f + expf(-(d[0] + bias[o])));
                float g1 = 1.0f / (1.0f + expf(-(d[1] + bias[o + 1])));
                if (rpath) {
                    float rh0 = g0 * g_h[row * HID + o];
                    float rh1 = g1 * g_h[row * HID + o + 1];
                    __half h0 = __float2half(rh0), h1 = __float2half(rh1);
                    *(__half2*)&g_dyn2[row * 384 + o] = __halves2half2(h0, h1);
                    g_RT[((size_t)bidx * 128 + o) * NNODE + node] = h0;
                    g_RT[((size_t)bidx * 128 + o + 1) * NNODE + node] = h1;
                } else {
                    *(float2*)&g_u[row * HID + (o - 128)] = make_float2(g0, g1);
                }
            }
        }
    }
}

// ---------------------------------------------------------------------------
// Candidate GEMM (K=768, N-tile 64), tanh + GRU update. grid(128, 2).
// Writes g_h fp32, dyn1 h fp16, g_HT (h^T), and step output.
// ---------------------------------------------------------------------------
__global__ __launch_bounds__(256) void cand_tc(const float* __restrict__ bias,
                                               int t, int l, float* __restrict__ cur) {
    extern __shared__ __half sm[];
    const int m0 = blockIdx.x * 128, n0 = blockIdx.y * 64;
    const __half* A0 = xsrc_dev(l) + ((size_t)t * ROWS + m0) * DIN;
    const __half* A1 = g_XPRE + ((size_t)t * ROWS + m0) * 256;
    const __half* A2 = g_dyn2 + (size_t)m0 * 384;
    const __half* B = g_WcPT + (size_t)l * 128 * KTOT + (size_t)n0 * KTOT;
    float acc[8][4];
    mainloop3<24, 2>(A0, DIN, A1, 256, A2, 384, 4, 12, B, KTOT, sm, acc);

    const int lane = threadIdx.x & 31, warp = threadIdx.x >> 5;
    const int wm = warp >> 2, wn = warp & 3;
#pragma unroll
    for (int mt = 0; mt < 4; mt++) {
#pragma unroll
        for (int half = 0; half < 2; half++) {
            const size_t row = (size_t)m0 + wm * 64 + mt * 16 + (lane >> 2) + half * 8;
            const int bidx = (int)(row >> 9);
            const int node = (int)(row & 511);
#pragma unroll
            for (int nt = 0; nt < 2; nt++) {
                const int o = n0 + wn * 16 + nt * 8 + (lane & 3) * 2;
                const float* d = acc[mt * 2 + nt] + half * 2;
                const size_t idx = row * HID + o;
                float c0 = tanhf(d[0] + bias[o]);
                float c1 = tanhf(d[1] + bias[o + 1]);
                float u0 = g_u[idx], u1 = g_u[idx + 1];
                float h0 = u0 * g_h[idx] + (1.0f - u0) * c0;
                float h1 = u1 * g_h[idx + 1] + (1.0f - u1) * c1;
                *(float2*)&g_h[idx] = make_float2(h0, h1);
                __half hh0 = __float2half(h0), hh1 = __float2half(h1);
                __half2 hh = __halves2half2(hh0, hh1);
                *(__half2*)&g_dyn1[row * 384 + o] = hh;
                g_HT[((size_t)bidx * 128 + o) * NNODE + node] = hh0;
                g_HT[((size_t)bidx * 128 + o + 1) * NNODE + node] = hh1;
                if (l == 0)
                    *(__half2*)&g_l0out[((size_t)t * ROWS) * HID + idx] = hh;
                else
                    *(float2*)&cur[(size_t)t * BNH + idx] = make_float2(h0, h1);
            }
        }
    }
}

// ---------------------------------------------------------------------------
// xt_pack: build g_XT (x^T per (t,b)) for layer l. grid TS*128 blocks.
// ---------------------------------------------------------------------------
__global__ __launch_bounds__(256) void xt_pack(const float* __restrict__ inputs, int l) {
    __shared__ __half sm[128][136];
    const int blk = blockIdx.x;            // 0..4095
    const int t = blk >> 7;
    const int rb = blk & 127;
    const int b = rb >> 2;
    const int n0 = (rb & 3) * 128;
    const int tid = threadIdx.x;
    const size_t srcrow0 = (size_t)t * ROWS + (size_t)b * NNODE + n0;
    if (l == 0) {
        for (int it = 0; it < 64; it++) {
            int idx = it * 256 + tid;
            int rr = idx >> 7, cc = idx & 127;
            sm[rr][cc] = __float2half(inputs[(srcrow0 + rr) * DIN + cc]);
        }
    } else {
        for (int it = 0; it < 64; it++) {
            int idx = it * 256 + tid;
            int rr = idx >> 7, cc = idx & 127;
            sm[rr][cc] = g_l0out[(srcrow0 + rr) * HID + cc];
        }
    }
    __syncthreads();
    __half* dst = g_XT + ((size_t)t * BB + b) * (128 * NNODE);
    for (int it = 0; it < 64; it++) {
        int idx = it * 256 + tid;
        int f = idx >> 7, n = idx & 127;
        dst[(size_t)f * NNODE + n0 + n] = sm[n][f];
    }
}

// ---------------------------------------------------------------------------
// Setup kernels
// ---------------------------------------------------------------------------
__global__ __launch_bounds__(256) void m2_kernel(const float* __restrict__ S) {
    __shared__ float As[16][132];
    __shared__ float Bs[16][64];
    const int tid = threadIdx.x;
    const int m0 = blockIdx.x * 128, n0 = blockIdx.y * 64;
    const int tm = tid >> 4, tn = tid & 15;
    float acc[8][4];
#pragma unroll
    for (int i = 0; i < 8; i++)
#pragma unroll
        for (int j = 0; j < 4; j++) acc[i][j] = 0.f;
    for (int kt = 0; kt < NNODE; kt += 16) {
#pragma unroll
        for (int it = 0; it < 2; it++) {
            int idx = tid + it * 256;
            int row = idx >> 2, k4 = (idx & 3) * 4;
            float4 v = *(const float4*)&S[(size_t)(m0 + row) * NNODE + kt + k4];
            As[k4 + 0][row] = v.x; As[k4 + 1][row] = v.y;
            As[k4 + 2][row] = v.z; As[k4 + 3][row] = v.w;
        }
        {
            int krow = tid >> 4, f4 = (tid & 15) * 4;
            float4 v = *(const float4*)&S[(size_t)(kt + krow) * NNODE + n0 + f4];
            *(float4*)&Bs[krow][f4] = v;
        }
        __syncthreads();
#pragma unroll
        for (int kk = 0; kk < 16; kk++) {
            float a[8], bb[4];
#pragma unroll
            for (int i = 0; i < 8; i++) a[i] = As[kk][tm * 8 + i];
#pragma unroll
            for (int j = 0; j < 4; j++) bb[j] = Bs[kk][tn * 4 + j];
#pragma unroll
            for (int i = 0; i < 8; i++)
#pragma unroll
                for (int j = 0; j < 4; j++) acc[i][j] += a[i] * bb[j];
        }
        __syncthreads();
    }
#pragma unroll
    for (int i = 0; i < 8; i++) {
        int m = m0 + tm * 8 + i;
#pragma unroll
        for (int j = 0; j < 4; j++) {
            int n = n0 + tn * 4 + j;
            g_M2[(size_t)m * NNODE + n] = 2.0f * acc[i][j] - (m == n ? 1.0f : 0.0f);
        }
    }
}

__global__ void conv_mats(const float* __restrict__ S) {
    int i = blockIdx.x * 256 + threadIdx.x;
    g_S16[i] = __float2half(S[i]);
    g_M216[i] = __float2half(g_M2[i]);
}

// kp -> k permutation: regions [x, Sx, M2x, h, Sh, M2h]
__device__ __forceinline__ int kperm(int kp) {
    const int off[6] = {0, 128, 256, -256, -128, 0};
    return kp + off[kp >> 7];
}

__global__ void wtransP(const float* __restrict__ Wg, const float* __restrict__ Wc) {
    int i = blockIdx.x * 256 + threadIdx.x;
    if (i < 2 * 256 * KTOT) {
        int l = i / (256 * KTOT), rem = i % (256 * KTOT);
        int o = rem / KTOT, kp = rem % KTOT;
        g_WgPT[i] = __float2half(Wg[(size_t)l * KTOT * 256 + (size_t)kperm(kp) * 256 + o]);
    }
    if (i < 2 * 128 * KTOT) {
        int l = i / (128 * KTOT), rem = i % (128 * KTOT);
        int o = rem / KTOT, kp = rem % KTOT;
        g_WcPT[i] = __float2half(Wc[(size_t)l * KTOT * 128 + (size_t)kperm(kp) * 128 + o]);
    }
}

__global__ void packx0(const float* __restrict__ inputs) {
    size_t i = (size_t)blockIdx.x * 256 + threadIdx.x;
    float4 v = *(const float4*)&inputs[i * 4];
    *(__half2*)&g_X16[i * 4] = __floats2half2_rn(v.x, v.y);
    *(__half2*)&g_X16[i * 4 + 2] = __floats2half2_rn(v.z, v.w);
}

__global__ void init_h(const float* __restrict__ ihs, int l) {
    int i = (blockIdx.x * blockDim.x + threadIdx.x) * 4;
    float4 v = *(const float4*)&ihs[(size_t)l * BNH + i];
    *(float4*)&g_h[i] = v;
    int row = i >> 7, col = i & 127;
    *(__half2*)&g_dyn1[(size_t)row * 384 + col] = __floats2half2_rn(v.x, v.y);
    *(__half2*)&g_dyn1[(size_t)row * 384 + col + 2] = __floats2half2_rn(v.z, v.w);
    int b = row >> 9, node = row & 511;
    g_HT[((size_t)b * 128 + col + 0) * NNODE + node] = __float2half(v.x);
    g_HT[((size_t)b * 128 + col + 1) * NNODE + node] = __float2half(v.y);
    g_HT[((size_t)b * 128 + col + 2) * NNODE + node] = __float2half(v.z);
    g_HT[((size_t)b * 128 + col + 3) * NNODE + node] = __float2half(v.w);
}

__global__ void copy_final(float* __restrict__ out, int l) {
    int i = (blockIdx.x * blockDim.x + threadIdx.x) * 4;
    *(float4*)&out[(size_t)l * BNH + i] = *(const float4*)&g_h[i];
}

// ---------------------------------------------------------------------------
extern "C" void kernel_launch(void* const* d_in, const int* in_sizes, int n_in,
                              void* d_out, int out_size) {
    const float* inputs = (const float*)d_in[0];
    const float* ihs    = (const float*)d_in[1];
    const float* S      = (const float*)d_in[2];
    const float* Wg     = (const float*)d_in[3];
    const float* bg     = (const float*)d_in[4];
    const float* Wc     = (const float*)d_in[5];
    const float* bc     = (const float*)d_in[6];
    float* out = (float*)d_out;
    float* cur = out + FINALS;

    cudaFuncSetAttribute(diff_step, cudaFuncAttributeMaxDynamicSharedMemorySize, SMEM_DIFF);
    cudaFuncSetAttribute(bigdiff,   cudaFuncAttributeMaxDynamicSharedMemorySize, SMEM_DIFF);
    cudaFuncSetAttribute(gate_tc,   cudaFuncAttributeMaxDynamicSharedMemorySize, SMEM_GATE);
    cudaFuncSetAttribute(cand_tc,   cudaFuncAttributeMaxDynamicSharedMemorySize, SMEM_CAND);

    m2_kernel<<<dim3(4, 8), 256>>>(S);
    conv_mats<<<1024, 256>>>(S);
    wtransP<<<1536, 256>>>(Wg, Wc);
    packx0<<<65536, 256>>>(inputs);

    for (int l = 0; l < 2; l++) {
        xt_pack<<<TS * 128, 256>>>(inputs, l);
        bigdiff<<<dim3(4, TS, 64), 256, SMEM_DIFF>>>();
        init_h<<<2048, 256>>>(ihs, l);
        for (int t = 0; t < TS; t++) {
            diff_step<<<dim3(4, 1, 64), 256, SMEM_DIFF>>>(0);   // h  -> Sh  | M2h
            gate_tc<<<dim3(128, 2), 256, SMEM_GATE>>>(bg + (size_t)l * 256, t, l);
            diff_step<<<dim3(4, 1, 64), 256, SMEM_DIFF>>>(1);   // rh -> Srh | M2rh
            cand_tc<<<dim3(128, 2), 256, SMEM_CAND>>>(bc + (size_t)l * 128, t, l, cur);
        }
        copy_final<<<2048, 256>>>(out, l);
    }
}